// round 17
// baseline (speedup 1.0000x reference)
#include <cuda_runtime.h>
#include <cstdint>

#define BB 128
#define TT 4096
#define KK 64
#define START 62
#define STOP 63
#define NEGV -10000.0f

// plain u8 backpointers
__device__ unsigned char g_bp[(size_t)BB * TT * KK];   // 32 MB

__device__ __forceinline__ void barn(int id, int cnt) {
    asm volatile("bar.sync %0, %1;" :: "r"(id), "r"(cnt) : "memory");
}

__global__ __launch_bounds__(512, 1)
void crf_kernel(const float* __restrict__ feats,
                const int*   __restrict__ tags,
                const float* __restrict__ trans,
                float*       __restrict__ out)
{
    __shared__ __align__(16) float a_buf[2][2][KK];   // [chain][parity][state]
    __shared__ __align__(16) float d_buf[2][2][KK];
    __shared__ float tStop[KK];
    __shared__ float gred[2][64];
    __shared__ __align__(16) unsigned char stage[2][2][64 * KK];  // [chain][pp][4KB]

    const int tid = threadIdx.x;
    const int c   = tid >> 8;          // chain within CTA (0/1)
    const int l   = tid & 255;         // lane within chain group
    const int b   = blockIdx.x * 2 + c;
    const float* bf = feats + (size_t)b * TT * KK;
    unsigned char* bpb = g_bp + (size_t)b * TT * KK;
    float logscale = 0.0f;

    if (tid < KK) tStop[tid] = trans[STOP * KK + tid];
    if (l < KK) {
        a_buf[c][0][l] = (l == START) ? 1.0f : 0.0f;
        d_buf[c][0][l] = (l == START) ? 0.0f : NEGV;
    }
    __syncthreads();

    const int barMain = 1 + c * 2 + ((l < 128) ? 0 : 1);   // F: 1/3, V: 2/4

    if (l < 128) {
        // ========== FORWARD group (chain c): warps {0-3 | 8-11}, 2 thr/state ==========
        const int j = l >> 1;
        const int h = l & 1;
        float E[32];
#pragma unroll
        for (int i = 0; i < 32; i++) E[i] = __expf(trans[j * KK + h * 32 + i]);

        float f0 = bf[j], f1 = bf[KK + j];
        int p = 0;
        barn(barMain, 128);

        for (int t = 0; t < TT; t++) {
            float f2 = (t + 2 < TT) ? bf[(size_t)(t + 2) * KK + j] : 0.0f;

            const float4* av = (const float4*)(&a_buf[c][p][h * 32]);
            float c0, c1, c2, c3;
            float a0 = 0.f;
            {
                float4 A = av[0];
                a0 = A.x;                       // h==0: a_prev[0]
                c0 = E[0] * A.x; c1 = E[1] * A.y; c2 = E[2] * A.z; c3 = E[3] * A.w;
            }
#pragma unroll
            for (int k = 1; k < 8; k++) {
                float4 A = av[k];
                c0 = fmaf(E[4 * k + 0], A.x, c0);
                c1 = fmaf(E[4 * k + 1], A.y, c1);
                c2 = fmaf(E[4 * k + 2], A.z, c2);
                c3 = fmaf(E[4 * k + 3], A.w, c3);
            }
            float dot = (c0 + c1) + (c2 + c3);
            dot += __shfl_xor_sync(0xffffffffu, dot, 1);

            if (h == 0) {
                float Ma = (t == 0) ? 1.0f : a0;
                a_buf[c][p ^ 1][j] = __fdividef(__expf(f0) * dot, Ma);
                if (l == 0) logscale += __logf(Ma);
            }
            barn(barMain, 128);
            p ^= 1;
            f0 = f1; f1 = f2;
        }
    } else {
        // ========== VITERBI group (chain c): warps {4-7 | 12-15}, 2 thr/state ==========
        const int vt = l - 128;
        const int j = vt >> 1;
        const int h = vt & 1;
        float T[32];
#pragma unroll
        for (int i = 0; i < 32; i++) T[i] = trans[j * KK + h * 32 + i];

        float f0 = bf[j], f1 = bf[KK + j];
        int p = 0;
        barn(barMain, 128);

        for (int t = 0; t < TT; t++) {
            float f2 = (t + 2 < TT) ? bf[(size_t)(t + 2) * KK + j] : 0.0f;

            const float4* dv = (const float4*)(&d_buf[c][p][h * 32]);
            float v[32];
#pragma unroll
            for (int k = 0; k < 8; k++) {
                float4 D = dv[k];
                v[4 * k + 0] = T[4 * k + 0] + D.x;
                v[4 * k + 1] = T[4 * k + 1] + D.y;
                v[4 * k + 2] = T[4 * k + 2] + D.z;
                v[4 * k + 3] = T[4 * k + 3] + D.w;
            }
            float m0 = v[0], m1 = v[1], m2 = v[2], m3 = v[3];
#pragma unroll
            for (int k = 1; k < 8; k++) {
                m0 = fmaxf(m0, v[4 * k + 0]);
                m1 = fmaxf(m1, v[4 * k + 1]);
                m2 = fmaxf(m2, v[4 * k + 2]);
                m3 = fmaxf(m3, v[4 * k + 3]);
            }
            float Mh = fmaxf(fmaxf(m0, m1), fmaxf(m2, m3));
            float M  = fmaxf(Mh, __shfl_xor_sync(0xffffffffu, Mh, 1));

            unsigned msk0 = 0, msk1 = 0, msk2 = 0, msk3 = 0;
#pragma unroll
            for (int k = 0; k < 8; k++) {
                msk0 |= (v[4 * k + 0] == M) ? (1u << (4 * k + 0)) : 0u;
                msk1 |= (v[4 * k + 1] == M) ? (1u << (4 * k + 1)) : 0u;
                msk2 |= (v[4 * k + 2] == M) ? (1u << (4 * k + 2)) : 0u;
                msk3 |= (v[4 * k + 3] == M) ? (1u << (4 * k + 3)) : 0u;
            }
            unsigned msk = (msk0 | msk1) | (msk2 | msk3);
            int cand = msk ? (h * 32 + __ffs(msk) - 1) : 1000;
            int oc = __shfl_xor_sync(0xffffffffu, cand, 1);
            cand = min(cand, oc);

            if (h == 0) {
                d_buf[c][p ^ 1][j] = M + f0;
                bpb[(size_t)t * KK + j] = (unsigned char)cand;
            }
            barn(barMain, 128);
            p ^= 1;
            f0 = f1; f1 = f2;
        }
    }

    __syncthreads();   // final: a_buf[c][0] = a_TT, d_buf[c][0] = delta_TT

    if (l < 64) {
        // ---- gold score + nll (first 2 warps of chain's F group) ----
        const int* btags = tags + (size_t)b * TT;
        float g = 0.0f;
        for (int t = l; t < TT; t += 64) {
            int tag  = btags[t];
            int prev = t ? btags[t - 1] : START;
            g += trans[tag * KK + prev] + bf[(size_t)t * KK + tag];
        }
        gred[c][l] = g;
        barn(5 + c, 64);
        if (l == 0) {   // this thread held logscale through the main loop
            float gold = 0.0f;
            for (int i = 0; i < 64; i++) gold += gred[c][i];
            gold += tStop[btags[TT - 1]];
            float s = 0.0f;
            for (int i = 0; i < KK; i++) s += a_buf[c][0][i] * __expf(tStop[i]);
            out[b] = (logscale + __logf(s)) - gold;
        }
    } else if (l >= 128 && l < 192) {
        // ---- viterbi terminal + backtrack (first 2 warps of chain's V group) ----
        int cur = 0;
        float* po = out + 2 * BB + (size_t)b * TT;
        if (l == 128) {
            float best = -3.0e38f; int bl2 = 0;
            for (int i = 0; i < KK; i++) {
                float v = d_buf[c][0][i] + tStop[i];
                if (v > best) { best = v; bl2 = i; }
            }
            out[BB + b] = best;
            cur = bl2;
        }
        // preload chunk 63 into stage[c][1]
        {
            const uint4* src = (const uint4*)(bpb + (size_t)63 * 64 * KK);
            uint4* dst = (uint4*)stage[c][1];
            for (int i = l - 128; i < 256; i += 64) dst[i] = src[i];
        }
        barn(7 + c, 64);
        for (int ch = 63; ch >= 0; ch--) {
            if (l != 128 && ch > 0) {
                const uint4* src = (const uint4*)(bpb + (size_t)(ch - 1) * 64 * KK);
                uint4* dst = (uint4*)stage[c][(ch - 1) & 1];
                for (int i = l - 129; i < 256; i += 63) dst[i] = src[i];
            }
            if (l == 128) {
                const unsigned char* st = stage[c][ch & 1];
#pragma unroll 4
                for (int tt = 63; tt >= 0; tt--) {
                    po[ch * 64 + tt] = (float)cur;
                    cur = st[tt * KK + cur];
                }
            }
            barn(7 + c, 64);
        }
    }
}

extern "C" void kernel_launch(void* const* d_in, const int* in_sizes, int n_in,
                              void* d_out, int out_size)
{
    const float* feats = (const float*)d_in[0];
    const int*   tags  = (const int*)d_in[1];
    const float* trans = (const float*)d_in[2];
    float* out = (float*)d_out;
    crf_kernel<<<BB / 2, 512>>>(feats, tags, trans, out);
}